// round 14
// baseline (speedup 1.0000x reference)
#include <cuda_runtime.h>
#include <cuda_fp16.h>
#include <math.h>

// Fixed shapes: y_s, y_t : [4, 256, 32000] fp32
#define B 4
#define S 256
#define V 32000
#define BS (B * S)
#define KS 37                      // uneven K-split: 19 chunks of 14 stages, 18 of 13 (x64 halfs)
#define BM 128
#define BN 128
#define BK2 32                     // half2 per stage = 64 halfs
#define SCALE 8192.0f
#define INV2SCALE (2.0f / SCALE)

#define CD_SMEM (2 * 2 * BK2 * (BM + 4) * (int)sizeof(__half2))   // 67584
#define SINK_SMEM (S * (S / 2) * (int)sizeof(__half2))            // 131072

// ---------------- static device scratch ----------------
__device__ __half g_probe[2][BS * V];          // UNNORMALIZED exp(y/2) as half (131 MB)
__device__ __half2 g_rzh[2 * BS];              // per-row SCALE/Z as half2
__device__ float g_part[B * KS * S * S];       // K-split partial scaled sum-of-min
__device__ float g_W[B * S * S];
__device__ float g_loss[B];

// ---------------- phase 1 (fused): exp + row-sum stats, single pass over y ----------------
__global__ void stats_kernel(const float* __restrict__ ys, const float* __restrict__ yt) {
    int row = blockIdx.x;
    int tensor = blockIdx.y;
    const float* y = (tensor ? yt : ys) + (size_t)row * V;
    __half* e = g_probe[tensor] + (size_t)row * V;
    int tid = threadIdx.x;

    float Z = 0.f;
    for (int f = tid; f < V / 4; f += 256) {
        float4 v = ((const float4*)y)[f];
        float e0 = __expf(v.x * 0.5f);
        float e1 = __expf(v.y * 0.5f);
        float e2 = __expf(v.z * 0.5f);
        float e3 = __expf(v.w * 0.5f);
        Z += (e0 + e1) + (e2 + e3);
        __half2 h[2];
        h[0] = __floats2half2_rn(e0, e1);
        h[1] = __floats2half2_rn(e2, e3);
        ((uint2*)e)[f] = *(uint2*)h;
    }

    __shared__ float sz[256];
    sz[tid] = Z;
    __syncthreads();
    for (int s = 128; s > 0; s >>= 1) {
        if (tid < s) sz[tid] += sz[tid + s];
        __syncthreads();
    }
    if (tid == 0) {
        float r = SCALE / sz[0];
        g_rzh[tensor * BS + row] = __floats2half2_rn(r, r);
    }
}

// ---------------- phase 2: half2 sum-of-min "GEMM", flush every 2 stages ----------------
__global__ void __launch_bounds__(512, 1) cdist_kernel() {
    extern __shared__ __align__(16) __half2 dyn[];
    typedef __half2 ST[BK2][BM + 4];
    ST* sa2 = (ST*)dyn;                         // [2][BK2][BM+4]
    ST* sb2 = (ST*)(dyn + 2 * BK2 * (BM + 4));  // [2][BK2][BN+4]

    int t  = threadIdx.x;
    int it = blockIdx.x >> 1;      // 0..1
    int jt = blockIdx.x & 1;       // 0..1
    int ks = blockIdx.y;           // 0..36
    int b  = blockIdx.z;

    int st0 = (ks < 19) ? 14 * ks : 13 * ks + 19;   // chunk start in 64-half units
    int nst = (ks < 19) ? 14 : 13;

    const __half* A  = g_probe[0] + (size_t)(b * S + it * BM) * V + st0 * 64;
    const __half* Bp = g_probe[1] + (size_t)(b * S + jt * BN) * V + st0 * 64;

    int lrow = t >> 2, lq = t & 3;               // loader: 128 rows x 4 threads x 2 uint4
    const uint4* pa = (const uint4*)(A  + (size_t)lrow * V);
    const uint4* pb = (const uint4*)(Bp + (size_t)lrow * V);
    __half2 ra = g_rzh[b * S + it * BM + lrow];
    __half2 rb = g_rzh[BS + b * S + jt * BN + lrow];

    int tx = t & 31;               // col group (4 cols) -> conflict-free 16B-stride LDS
    int ty = t >> 5;               // row group (8 rows) -> broadcast LDS

    uint4 ga[2], gb[2];
    float acc[8][4];
    __half2 hacc[8][4];
#pragma unroll
    for (int i = 0; i < 8; i++)
#pragma unroll
        for (int j = 0; j < 4; j++) acc[i][j] = 0.f;

    // prologue: stage 0 -> buf 0, prefetch stage 1 into regs
#pragma unroll
    for (int u = 0; u < 2; u++) { ga[u] = pa[lq * 2 + u]; gb[u] = pb[lq * 2 + u]; }
#pragma unroll
    for (int u = 0; u < 2; u++) {
        const __half2* ha = (const __half2*)&ga[u];
        const __half2* hb = (const __half2*)&gb[u];
#pragma unroll
        for (int j = 0; j < 4; j++) {
            sa2[0][(lq * 2 + u) * 4 + j][lrow] = __hmul2(ha[j], ra);
            sb2[0][(lq * 2 + u) * 4 + j][lrow] = __hmul2(hb[j], rb);
        }
    }
    if (1 < nst) {
#pragma unroll
        for (int u = 0; u < 2; u++) { ga[u] = pa[8 + lq * 2 + u]; gb[u] = pb[8 + lq * 2 + u]; }
    }
    __syncthreads();

    for (int s = 0; s < nst; s++) {
        int cur = s & 1, nxt = cur ^ 1;
        if (s + 1 < nst) {         // store regs (stage s+1) into other buffer
#pragma unroll
            for (int u = 0; u < 2; u++) {
                const __half2* ha = (const __half2*)&ga[u];
                const __half2* hb = (const __half2*)&gb[u];
#pragma unroll
                for (int j = 0; j < 4; j++) {
                    sa2[nxt][(lq * 2 + u) * 4 + j][lrow] = __hmul2(ha[j], ra);
                    sb2[nxt][(lq * 2 + u) * 4 + j][lrow] = __hmul2(hb[j], rb);
                }
            }
        }
        if (s + 2 < nst) {         // prefetch stage s+2 into regs
            int base = (s + 2) * 8;
#pragma unroll
            for (int u = 0; u < 2; u++) { ga[u] = pa[base + lq * 2 + u]; gb[u] = pb[base + lq * 2 + u]; }
        }

        if ((s & 1) == 0) {        // init half accumulators every other stage
#pragma unroll
            for (int i = 0; i < 8; i++)
#pragma unroll
                for (int j = 0; j < 4; j++) hacc[i][j] = __float2half2_rn(0.f);
        }

#pragma unroll 8
        for (int kk2 = 0; kk2 < BK2; kk2++) {
            float4 fa0 = *(const float4*)&sa2[cur][kk2][ty * 8];
            float4 fa1 = *(const float4*)&sa2[cur][kk2][ty * 8 + 4];
            float4 fb  = *(const float4*)&sb2[cur][kk2][tx * 4];
            __half2 a[8], c[4];
            *(float4*)&a[0] = fa0; *(float4*)&a[4] = fa1;
            *(float4*)&c[0] = fb;
#pragma unroll
            for (int i = 0; i < 8; i++)
#pragma unroll
                for (int j = 0; j < 4; j++)
                    hacc[i][j] = __hadd2(hacc[i][j], __hmin2(a[i], c[j]));
        }

        if ((s & 1) == 1 || s == nst - 1) {   // flush to fp32 every 2 stages (or at end)
#pragma unroll
            for (int i = 0; i < 8; i++)
#pragma unroll
                for (int j = 0; j < 4; j++) {
                    float2 f = __half22float2(hacc[i][j]);
                    acc[i][j] += f.x + f.y;
                }
        }
        __syncthreads();
    }

    float* out = g_part + (size_t)(b * KS + ks) * (S * S)
               + (it * BM + ty * 8) * S + jt * BN + tx * 4;
#pragma unroll
    for (int i = 0; i < 8; i++)
        *(float4*)(out + i * S) = make_float4(acc[i][0], acc[i][1], acc[i][2], acc[i][3]);
}

// ---------------- phase 3: K-split reduce -> W = 2 - 2*summin ----------------
__global__ void reduceW_kernel() {
    int idx = blockIdx.x * 256 + threadIdx.x;
    int b  = idx >> 16;
    int ij = idx & 65535;
    float s = 0.f;
#pragma unroll
    for (int ks = 0; ks < KS; ks++)
        s += g_part[(size_t)(b * KS + ks) * (S * S) + ij];
    g_W[idx] = 2.0f - s * INV2SCALE;
}

// ---------------- phase 4: Sinkhorn in scaling-vector form ----------------
// K' = rownorm(exp(-10W)) stored ONCE in smem (half2, read-only).
// Iterate u = 1/(K'v), v = 1/(K'^T u) in fp32.  P_final = diag(u) K' diag(v).
__global__ void __launch_bounds__(1024) sinkhorn_kernel() {
    extern __shared__ __align__(16) __half2 sK[];   // [256][128] half2 = 128 KB
    __shared__ float cpart[32][256];
    __shared__ float spart[4][256];
    __shared__ float su[256], sv[256];
    __shared__ float red[32];

    int b = blockIdx.x, t = threadIdx.x;
    int w = t >> 5, l = t & 31;
    const float* W = g_W + (size_t)b * (S * S);
    uint4* sKu = (uint4*)sK;

    if (t < 256) sv[t] = 1.0f;

    // init: K' = exp(-10W) row-normalized in fp32, stored half
#pragma unroll
    for (int r = 0; r < 8; r++) {
        int row = w * 8 + r;
        float4 a = ((const float4*)(W + row * 256))[2 * l];
        float4 c = ((const float4*)(W + row * 256))[2 * l + 1];
        float e[8];
        e[0] = __expf(-10.f * a.x); e[1] = __expf(-10.f * a.y);
        e[2] = __expf(-10.f * a.z); e[3] = __expf(-10.f * a.w);
        e[4] = __expf(-10.f * c.x); e[5] = __expf(-10.f * c.y);
        e[6] = __expf(-10.f * c.z); e[7] = __expf(-10.f * c.w);
        float rs = (e[0] + e[1]) + (e[2] + e[3]) + (e[4] + e[5]) + (e[6] + e[7]);
#pragma unroll
        for (int o = 16; o; o >>= 1) rs += __shfl_xor_sync(0xffffffffu, rs, o);
        float ri = 1.0f / rs;
        __half2 h[4];
#pragma unroll
        for (int j = 0; j < 4; j++)
            h[j] = __floats2half2_rn(e[2 * j] * ri, e[2 * j + 1] * ri);
        sKu[row * 32 + l] = *(uint4*)h;
    }
    __syncthreads();

    for (int iter = 0; iter < 10; iter++) {
        // u = 1/(K' v): warp-per-8-rows matvec
        float4 v0 = ((const float4*)sv)[2 * l];
        float4 v1 = ((const float4*)sv)[2 * l + 1];
#pragma unroll
        for (int r = 0; r < 8; r++) {
            int row = w * 8 + r;
            uint4 ku = sKu[row * 32 + l];
            const __half2* ph = (const __half2*)&ku;
            float2 f0 = __half22float2(ph[0]);
            float2 f1 = __half22float2(ph[1]);
            float2 f2 = __half22float2(ph[2]);
            float2 f3 = __half22float2(ph[3]);
            float s = f0.x * v0.x + f0.y * v0.y + f1.x * v0.z + f1.y * v0.w
                    + f2.x * v1.x + f2.y * v1.y + f3.x * v1.z + f3.y * v1.w;
#pragma unroll
            for (int o = 16; o; o >>= 1) s += __shfl_xor_sync(0xffffffffu, s, o);
            if (l == 0) su[row] = 1.0f / s;
        }
        __syncthreads();

        // v = 1/(K'^T u): per-thread col partials, cross-warp reduce
        float cp[8];
#pragma unroll
        for (int j = 0; j < 8; j++) cp[j] = 0.f;
#pragma unroll
        for (int r = 0; r < 8; r++) {
            int row = w * 8 + r;
            float ur = su[row];
            uint4 ku = sKu[row * 32 + l];
            const __half2* ph = (const __half2*)&ku;
            float2 f0 = __half22float2(ph[0]);
            float2 f1 = __half22float2(ph[1]);
            float2 f2 = __half22float2(ph[2]);
            float2 f3 = __half22float2(ph[3]);
            cp[0] += f0.x * ur; cp[1] += f0.y * ur;
            cp[2] += f1.x * ur; cp[3] += f1.y * ur;
            cp[4] += f2.x * ur; cp[5] += f2.y * ur;
            cp[6] += f3.x * ur; cp[7] += f3.y * ur;
        }
        ((float4*)cpart[w])[2 * l]     = make_float4(cp[0], cp[1], cp[2], cp[3]);
        ((float4*)cpart[w])[2 * l + 1] = make_float4(cp[4], cp[5], cp[6], cp[7]);
        __syncthreads();
        {
            int c = t & 255, g = t >> 8;
            float s = 0.f;
#pragma unroll
            for (int k = 0; k < 8; k++) s += cpart[g * 8 + k][c];
            spart[g][c] = s;
        }
        __syncthreads();
        if (t < 256)
            sv[t] = 1.0f / (spart[0][t] + spart[1][t] + spart[2][t] + spart[3][t]);
        __syncthreads();
    }

    // loss = sum_ij u_i K'_ij v_j W_ij
    float4 v0 = ((const float4*)sv)[2 * l];
    float4 v1 = ((const float4*)sv)[2 * l + 1];
    float acc = 0.f;
#pragma unroll
    for (int r = 0; r < 8; r++) {
        int row = w * 8 + r;
        float ur = su[row];
        uint4 ku = sKu[row * 32 + l];
        const __half2* ph = (const __half2*)&ku;
        float4 a = ((const float4*)(W + row * 256))[2 * l];
        float4 c = ((const float4*)(W + row * 256))[2 * l + 1];
        float2 f0 = __half22float2(ph[0]);
        float2 f1 = __half22float2(ph[1]);
        float2 f2 = __half22float2(ph[2]);
        float2 f3 = __half22float2(ph[3]);
        float s = f0.x * v0.x * a.x + f0.y * v0.y * a.y
                + f1.x * v0.z * a.z + f1.y * v0.w * a.w
                + f2.x * v1.x * c.x + f2.y * v1.y * c.y
                + f3.x * v1.z * c.z + f3.y * v1.w * c.w;
        acc += ur * s;
    }
#pragma unroll
    for (int o = 16; o; o >>= 1) acc += __shfl_xor_sync(0xffffffffu, acc, o);
    if (l == 0) red[w] = acc;
    __syncthreads();
    if (t == 0) {
        float s = 0.f;
        for (int k = 0; k < 32; k++) s += red[k];
        g_loss[b] = s;
    }
}

__global__ void finalize_kernel(float* out) {
    out[0] = 0.001f * (g_loss[0] + g_loss[1] + g_loss[2] + g_loss[3]);
}

// ---------------- launch ----------------
extern "C" void kernel_launch(void* const* d_in, const int* in_sizes, int n_in,
                              void* d_out, int out_size) {
    const float* ys = (const float*)d_in[0];
    const float* yt = (const float*)d_in[1];

    cudaFuncSetAttribute(cdist_kernel, cudaFuncAttributeMaxDynamicSharedMemorySize, CD_SMEM);
    cudaFuncSetAttribute(sinkhorn_kernel, cudaFuncAttributeMaxDynamicSharedMemorySize, SINK_SMEM);

    stats_kernel<<<dim3(BS, 2), 256>>>(ys, yt);
    cdist_kernel<<<dim3(4, KS, B), 512, CD_SMEM>>>();
    reduceW_kernel<<<dim3(B * S * S / 256), 256>>>();
    sinkhorn_kernel<<<B, 1024, SINK_SMEM>>>();
    finalize_kernel<<<1, 1>>>((float*)d_out);
}

// round 15
// speedup vs baseline: 1.0212x; 1.0212x over previous
#include <cuda_runtime.h>
#include <cuda_fp16.h>
#include <math.h>

// Fixed shapes: y_s, y_t : [4, 256, 32000] fp32
#define B 4
#define S 256
#define V 32000
#define BS (B * S)
#define KS 37                      // uneven K-split: 19 chunks of 14 stages, 18 of 13 (x64 halfs)
#define BM 128
#define BN 128
#define BK2 32                     // half2 per stage = 64 halfs
#define SCALE 8192.0f
#define INV2SCALE (2.0f / SCALE)

#define CD_SMEM (2 * 2 * BK2 * (BM + 4) * (int)sizeof(__half2))   // 67584
#define SINK_SMEM (S * (S / 2) * (int)sizeof(__half2))            // 131072

// ---------------- static device scratch ----------------
__device__ __half g_probe[2][BS * V];          // UNNORMALIZED exp(y/2) as half (131 MB)
__device__ __half2 g_rzh[2 * BS];              // per-row SCALE/Z as half2
__device__ float g_part[B * KS * S * S];       // K-split partial scaled sum-of-min
__device__ float g_W[B * S * S];
__device__ float g_loss[B];

// ---------------- phase 1 (fused): exp + row-sum stats, single pass over y ----------------
__global__ void stats_kernel(const float* __restrict__ ys, const float* __restrict__ yt) {
    int row = blockIdx.x;
    int tensor = blockIdx.y;
    const float* y = (tensor ? yt : ys) + (size_t)row * V;
    __half* e = g_probe[tensor] + (size_t)row * V;
    int tid = threadIdx.x;

    float Z = 0.f;
    for (int f = tid; f < V / 4; f += 256) {
        float4 v = ((const float4*)y)[f];
        float e0 = __expf(v.x * 0.5f);
        float e1 = __expf(v.y * 0.5f);
        float e2 = __expf(v.z * 0.5f);
        float e3 = __expf(v.w * 0.5f);
        Z += (e0 + e1) + (e2 + e3);
        __half2 h[2];
        h[0] = __floats2half2_rn(e0, e1);
        h[1] = __floats2half2_rn(e2, e3);
        ((uint2*)e)[f] = *(uint2*)h;
    }

    __shared__ float sz[256];
    sz[tid] = Z;
    __syncthreads();
    for (int s = 128; s > 0; s >>= 1) {
        if (tid < s) sz[tid] += sz[tid + s];
        __syncthreads();
    }
    if (tid == 0) {
        float r = SCALE / sz[0];
        g_rzh[tensor * BS + row] = __floats2half2_rn(r, r);
    }
}

// ---------------- phase 2: half2 sum-of-min "GEMM", flush every 2 stages ----------------
__global__ void __launch_bounds__(512, 1) cdist_kernel() {
    extern __shared__ __align__(16) __half2 dyn[];
    typedef __half2 ST[BK2][BM + 4];
    ST* sa2 = (ST*)dyn;                         // [2][BK2][BM+4]
    ST* sb2 = (ST*)(dyn + 2 * BK2 * (BM + 4));  // [2][BK2][BN+4]

    int t  = threadIdx.x;
    int it = blockIdx.x >> 1;      // 0..1
    int jt = blockIdx.x & 1;       // 0..1
    int ks = blockIdx.y;           // 0..36
    int b  = blockIdx.z;

    int st0 = (ks < 19) ? 14 * ks : 13 * ks + 19;   // chunk start in 64-half units
    int nst = (ks < 19) ? 14 : 13;

    const __half* A  = g_probe[0] + (size_t)(b * S + it * BM) * V + st0 * 64;
    const __half* Bp = g_probe[1] + (size_t)(b * S + jt * BN) * V + st0 * 64;

    int lrow = t >> 2, lq = t & 3;               // loader: 128 rows x 4 threads x 2 uint4
    const uint4* pa = (const uint4*)(A  + (size_t)lrow * V);
    const uint4* pb = (const uint4*)(Bp + (size_t)lrow * V);
    __half2 ra = g_rzh[b * S + it * BM + lrow];
    __half2 rb = g_rzh[BS + b * S + jt * BN + lrow];

    int tx = t & 31;               // col group (4 cols) -> conflict-free 16B-stride LDS
    int ty = t >> 5;               // row group (8 rows) -> broadcast LDS

    uint4 ga[2], gb[2];
    float acc[8][4];
    __half2 hacc[8][4];
#pragma unroll
    for (int i = 0; i < 8; i++)
#pragma unroll
        for (int j = 0; j < 4; j++) acc[i][j] = 0.f;

    // prologue: stage 0 -> buf 0, prefetch stage 1 into regs
#pragma unroll
    for (int u = 0; u < 2; u++) { ga[u] = pa[lq * 2 + u]; gb[u] = pb[lq * 2 + u]; }
#pragma unroll
    for (int u = 0; u < 2; u++) {
        const __half2* ha = (const __half2*)&ga[u];
        const __half2* hb = (const __half2*)&gb[u];
#pragma unroll
        for (int j = 0; j < 4; j++) {
            sa2[0][(lq * 2 + u) * 4 + j][lrow] = __hmul2(ha[j], ra);
            sb2[0][(lq * 2 + u) * 4 + j][lrow] = __hmul2(hb[j], rb);
        }
    }
    if (1 < nst) {
#pragma unroll
        for (int u = 0; u < 2; u++) { ga[u] = pa[8 + lq * 2 + u]; gb[u] = pb[8 + lq * 2 + u]; }
    }
    __syncthreads();

    for (int s = 0; s < nst; s++) {
        int cur = s & 1, nxt = cur ^ 1;
        if (s + 1 < nst) {         // store regs (stage s+1) into other buffer
#pragma unroll
            for (int u = 0; u < 2; u++) {
                const __half2* ha = (const __half2*)&ga[u];
                const __half2* hb = (const __half2*)&gb[u];
#pragma unroll
                for (int j = 0; j < 4; j++) {
                    sa2[nxt][(lq * 2 + u) * 4 + j][lrow] = __hmul2(ha[j], ra);
                    sb2[nxt][(lq * 2 + u) * 4 + j][lrow] = __hmul2(hb[j], rb);
                }
            }
        }
        if (s + 2 < nst) {         // prefetch stage s+2 into regs
            int base = (s + 2) * 8;
#pragma unroll
            for (int u = 0; u < 2; u++) { ga[u] = pa[base + lq * 2 + u]; gb[u] = pb[base + lq * 2 + u]; }
        }

        if ((s & 1) == 0) {        // init half accumulators every other stage
#pragma unroll
            for (int i = 0; i < 8; i++)
#pragma unroll
                for (int j = 0; j < 4; j++) hacc[i][j] = __float2half2_rn(0.f);
        }

#pragma unroll 8
        for (int kk2 = 0; kk2 < BK2; kk2++) {
            float4 fa0 = *(const float4*)&sa2[cur][kk2][ty * 8];
            float4 fa1 = *(const float4*)&sa2[cur][kk2][ty * 8 + 4];
            float4 fb  = *(const float4*)&sb2[cur][kk2][tx * 4];
            __half2 a[8], c[4];
            *(float4*)&a[0] = fa0; *(float4*)&a[4] = fa1;
            *(float4*)&c[0] = fb;
#pragma unroll
            for (int i = 0; i < 8; i++)
#pragma unroll
                for (int j = 0; j < 4; j++)
                    hacc[i][j] = __hadd2(hacc[i][j], __hmin2(a[i], c[j]));
        }

        if ((s & 1) == 1 || s == nst - 1) {   // flush to fp32 every 2 stages (or at end)
#pragma unroll
            for (int i = 0; i < 8; i++)
#pragma unroll
                for (int j = 0; j < 4; j++) {
                    float2 f = __half22float2(hacc[i][j]);
                    acc[i][j] += f.x + f.y;
                }
        }
        __syncthreads();
    }

    float* out = g_part + (size_t)(b * KS + ks) * (S * S)
               + (it * BM + ty * 8) * S + jt * BN + tx * 4;
#pragma unroll
    for (int i = 0; i < 8; i++)
        *(float4*)(out + i * S) = make_float4(acc[i][0], acc[i][1], acc[i][2], acc[i][3]);
}

// ---------------- phase 3: K-split reduce -> W = 2 - 2*summin ----------------
__global__ void reduceW_kernel() {
    int idx = blockIdx.x * 256 + threadIdx.x;
    int b  = idx >> 16;
    int ij = idx & 65535;
    float s = 0.f;
#pragma unroll
    for (int ks = 0; ks < KS; ks++)
        s += g_part[(size_t)(b * KS + ks) * (S * S) + ij];
    g_W[idx] = 2.0f - s * INV2SCALE;
}

// ---------------- phase 4: Sinkhorn u/v, fused passes, register-resident u, 2 barriers/iter ----------------
// K' = rownorm(exp(-10W)) in smem (half2, read-only). warp w owns rows 8w..8w+7,
// lane l owns cols 8l..8l+7. u lives ONLY in registers (all lanes hold it post-shuffle).
__global__ void __launch_bounds__(1024) sinkhorn_kernel() {
    extern __shared__ __align__(16) __half2 sK[];   // [256][128] half2 = 128 KB
    __shared__ float cpart[32][256];
    __shared__ float sv[256];
    __shared__ float red[32];

    int b = blockIdx.x, t = threadIdx.x;
    int w = t >> 5, l = t & 31;
    const float* W = g_W + (size_t)b * (S * S);
    uint4* sKu = (uint4*)sK;

    if (t < 256) sv[t] = 1.0f;
    float uinv[8];

    // init: K' = exp(-10W) row-normalized in fp32, stored half
#pragma unroll
    for (int r = 0; r < 8; r++) {
        int row = w * 8 + r;
        float4 a = ((const float4*)(W + row * 256))[2 * l];
        float4 c = ((const float4*)(W + row * 256))[2 * l + 1];
        float e[8];
        e[0] = __expf(-10.f * a.x); e[1] = __expf(-10.f * a.y);
        e[2] = __expf(-10.f * a.z); e[3] = __expf(-10.f * a.w);
        e[4] = __expf(-10.f * c.x); e[5] = __expf(-10.f * c.y);
        e[6] = __expf(-10.f * c.z); e[7] = __expf(-10.f * c.w);
        float rs = (e[0] + e[1]) + (e[2] + e[3]) + (e[4] + e[5]) + (e[6] + e[7]);
#pragma unroll
        for (int o = 16; o; o >>= 1) rs += __shfl_xor_sync(0xffffffffu, rs, o);
        float ri = 1.0f / rs;
        __half2 h[4];
#pragma unroll
        for (int j = 0; j < 4; j++)
            h[j] = __floats2half2_rn(e[2 * j] * ri, e[2 * j + 1] * ri);
        sKu[row * 32 + l] = *(uint4*)h;
    }
    __syncthreads();   // covers sK stores + sv init

    for (int iter = 0; iter < 10; iter++) {
        float4 v0 = ((const float4*)sv)[2 * l];
        float4 v1 = ((const float4*)sv)[2 * l + 1];
        float cp[8];
#pragma unroll
        for (int j = 0; j < 8; j++) cp[j] = 0.f;

        // fused u-pass + v-partials: one K read per row per iteration
#pragma unroll
        for (int r = 0; r < 8; r++) {
            int row = w * 8 + r;
            uint4 ku = sKu[row * 32 + l];
            const __half2* ph = (const __half2*)&ku;
            float2 f0 = __half22float2(ph[0]);
            float2 f1 = __half22float2(ph[1]);
            float2 f2 = __half22float2(ph[2]);
            float2 f3 = __half22float2(ph[3]);
            float s = f0.x * v0.x + f0.y * v0.y + f1.x * v0.z + f1.y * v0.w
                    + f2.x * v1.x + f2.y * v1.y + f3.x * v1.z + f3.y * v1.w;
#pragma unroll
            for (int o = 16; o; o >>= 1) s += __shfl_xor_sync(0xffffffffu, s, o);
            float ur = 1.0f / s;       // all lanes hold it — no smem, no barrier
            uinv[r] = ur;
            cp[0] += f0.x * ur; cp[1] += f0.y * ur;
            cp[2] += f1.x * ur; cp[3] += f1.y * ur;
            cp[4] += f2.x * ur; cp[5] += f2.y * ur;
            cp[6] += f3.x * ur; cp[7] += f3.y * ur;
        }
        ((float4*)cpart[w])[2 * l]     = make_float4(cp[0], cp[1], cp[2], cp[3]);
        ((float4*)cpart[w])[2 * l + 1] = make_float4(cp[4], cp[5], cp[6], cp[7]);
        __syncthreads();
        if (t < 256) {                 // one-step colsum over 32 warps
            float s = 0.f;
#pragma unroll
            for (int k = 0; k < 32; k++) s += cpart[k][t];
            sv[t] = 1.0f / s;
        }
        __syncthreads();
    }

    // loss = sum_ij u_i K'_ij v_j W_ij  (u from registers, v final in sv)
    float4 v0 = ((const float4*)sv)[2 * l];
    float4 v1 = ((const float4*)sv)[2 * l + 1];
    float acc = 0.f;
#pragma unroll
    for (int r = 0; r < 8; r++) {
        int row = w * 8 + r;
        float ur = uinv[r];
        uint4 ku = sKu[row * 32 + l];
        const __half2* ph = (const __half2*)&ku;
        float4 a = ((const float4*)(W + row * 256))[2 * l];
        float4 c = ((const float4*)(W + row * 256))[2 * l + 1];
        float2 f0 = __half22float2(ph[0]);
        float2 f1 = __half22float2(ph[1]);
        float2 f2 = __half22float2(ph[2]);
        float2 f3 = __half22float2(ph[3]);
        float s = f0.x * v0.x * a.x + f0.y * v0.y * a.y
                + f1.x * v0.z * a.z + f1.y * v0.w * a.w
                + f2.x * v1.x * c.x + f2.y * v1.y * c.y
                + f3.x * v1.z * c.z + f3.y * v1.w * c.w;
        acc += ur * s;
    }
#pragma unroll
    for (int o = 16; o; o >>= 1) acc += __shfl_xor_sync(0xffffffffu, acc, o);
    if (l == 0) red[w] = acc;
    __syncthreads();
    if (t == 0) {
        float s = 0.f;
        for (int k = 0; k < 32; k++) s += red[k];
        g_loss[b] = s;
    }
}

__global__ void finalize_kernel(float* out) {
    out[0] = 0.001f * (g_loss[0] + g_loss[1] + g_loss[2] + g_loss[3]);
}

// ---------------- launch ----------------
extern "C" void kernel_launch(void* const* d_in, const int* in_sizes, int n_in,
                              void* d_out, int out_size) {
    const float* ys = (const float*)d_in[0];
    const float* yt = (const float*)d_in[1];

    cudaFuncSetAttribute(cdist_kernel, cudaFuncAttributeMaxDynamicSharedMemorySize, CD_SMEM);
    cudaFuncSetAttribute(sinkhorn_kernel, cudaFuncAttributeMaxDynamicSharedMemorySize, SINK_SMEM);

    stats_kernel<<<dim3(BS, 2), 256>>>(ys, yt);
    cdist_kernel<<<dim3(4, KS, B), 512, CD_SMEM>>>();
    reduceW_kernel<<<dim3(B * S * S / 256), 256>>>();
    sinkhorn_kernel<<<B, 1024, SINK_SMEM>>>();
    finalize_kernel<<<1, 1>>>((float*)d_out);
}